// round 2
// baseline (speedup 1.0000x reference)
#include <cuda_runtime.h>

// VanillaSSM via exact diagonal linear recurrence (== reference FFT conv):
//   g[d,n](l) = A_bar[d,n] * g(l-1) + (C*B_bar)[d,n] * x[b,l,d]      (g := C*h)
//   y[b,l,d]  = sum_n g[d,n](l) + D[d] * x[b,l,d]
// A = -exp(log_A); A_bar = exp(DT*A); B_bar = (A_bar-1)/A * B_param.
//
// Block = 8 warps = 8 consecutive d, one batch b. Warp owns (b,d); each lane
// owns states n=2*... (n=lane, n=lane+32) packed in one 64-bit f32x2 register.
// Time in rounds of T=32: per-step packed partials are written (STS.64) into a
// padded smem buffer; each lane then reduces one timestep's 64 values with
// LDS.128 + add.f32x2. x loads / y stores staged via smem for full-sector
// coalescing (8 consecutive d per row = 32B sector).

namespace {

constexpr int BATCH   = 8;
constexpr int L       = 2048;
constexpr int D_MODEL = 1024;
constexpr int NSTATE  = 64;
constexpr float DT    = 0.1f;

constexpr int DPB     = 8;               // d per block (= warps)
constexpr int T       = 32;              // timesteps per round
constexpr int RS2     = 68;              // padded row stride in floats (64 data + 4 pad)
constexpr int NROUNDS = L / T;
constexpr int THREADS = DPB * 32;

constexpr int RED_FLOATS = DPB * T * RS2;          // 17408
constexpr int XS_FLOATS  = DPB * T;                // 256
constexpr int YS_FLOATS  = T * (DPB + 1);          // 288
constexpr int SMEM_BYTES = (RED_FLOATS + XS_FLOATS + YS_FLOATS) * 4;  // 71808

__device__ __forceinline__ unsigned long long pack2(float lo, float hi) {
    unsigned long long r;
    asm("mov.b64 %0, {%1, %2};" : "=l"(r) : "f"(lo), "f"(hi));
    return r;
}
__device__ __forceinline__ void unpack2(unsigned long long v, float& lo, float& hi) {
    asm("mov.b64 {%0, %1}, %2;" : "=f"(lo), "=f"(hi) : "l"(v));
}
__device__ __forceinline__ unsigned long long mul2(unsigned long long a, unsigned long long b) {
    unsigned long long r;
    asm("mul.rn.f32x2 %0, %1, %2;" : "=l"(r) : "l"(a), "l"(b));
    return r;
}
__device__ __forceinline__ unsigned long long fma2(unsigned long long a, unsigned long long b,
                                                   unsigned long long c) {
    unsigned long long r;
    asm("fma.rn.f32x2 %0, %1, %2, %3;" : "=l"(r) : "l"(a), "l"(b), "l"(c));
    return r;
}
__device__ __forceinline__ unsigned long long add2(unsigned long long a, unsigned long long b) {
    unsigned long long r;
    asm("add.rn.f32x2 %0, %1, %2;" : "=l"(r) : "l"(a), "l"(b));
    return r;
}

__global__ __launch_bounds__(THREADS)
void ssm_scan_kernel(const float* __restrict__ x,
                     const float* __restrict__ log_A,
                     const float* __restrict__ Bp,
                     const float* __restrict__ Cp,
                     const float* __restrict__ Dp,
                     float* __restrict__ y)
{
    extern __shared__ float smem[];
    float* red = smem;                        // [DPB][T * RS2]
    float* xs  = smem + RED_FLOATS;           // [DPB][T]
    float* ys  = xs + XS_FLOATS;              // [T][DPB+1]

    const int b    = blockIdx.y;
    const int d0   = blockIdx.x * DPB;
    const int tid  = threadIdx.x;
    const int w    = tid >> 5;                // warp id == d_local
    const int lane = tid & 31;
    const int d    = d0 + w;

    // ---- per-(d,n) coefficients, n = lane and lane+32, packed f32x2 ----
    const int cb = d * NSTATE + lane;
    const float A0  = -expf(log_A[cb]);
    const float A1  = -expf(log_A[cb + 32]);
    const float a0  = expf(DT * A0);          // A_bar in (0,1)
    const float a1  = expf(DT * A1);
    const float k0  = (a0 - 1.0f) / A0 * Bp[cb]      * Cp[cb];       // C*B_bar
    const float k1  = (a1 - 1.0f) / A1 * Bp[cb + 32] * Cp[cb + 32];
    const float Dd  = Dp[d];
    const unsigned long long a01 = pack2(a0, a1);
    const unsigned long long k01 = pack2(k0, k1);

    // cooperative tile mapping: thread -> (l within tile, d_local)
    const int ld = tid / DPB;
    const int dl = tid % DPB;
    const float* xg = x + (long)b * L * D_MODEL + d0 + dl;
    float*       yg = y + (long)b * L * D_MODEL + d0 + dl;

    float* redw = red + w * (T * RS2);
    float* xsw  = xs + w * T;

    unsigned long long g01 = 0ull;            // packed {g0, g1} = {0, 0}

    for (int r = 0; r < NROUNDS; ++r) {
        const int l0 = r * T;

        // stage x tile (full 32B sectors: 8 consecutive d per l)
        const float xv_in = xg[(l0 + ld) * D_MODEL];
        __syncthreads();                       // prev round's xs/ys consumed
        xs[dl * T + ld] = xv_in;
        __syncthreads();                       // xs ready

        // ---- core recurrence: 32 steps, packed 2 states/lane ----
#pragma unroll
        for (int t = 0; t < T; t += 4) {
            const float4 xq = *(const float4*)&xsw[t];
            g01 = fma2(a01, g01, mul2(k01, pack2(xq.x, xq.x)));
            *(unsigned long long*)&redw[(t + 0) * RS2 + 2 * lane] = g01;
            g01 = fma2(a01, g01, mul2(k01, pack2(xq.y, xq.y)));
            *(unsigned long long*)&redw[(t + 1) * RS2 + 2 * lane] = g01;
            g01 = fma2(a01, g01, mul2(k01, pack2(xq.z, xq.z)));
            *(unsigned long long*)&redw[(t + 2) * RS2 + 2 * lane] = g01;
            g01 = fma2(a01, g01, mul2(k01, pack2(xq.w, xq.w)));
            *(unsigned long long*)&redw[(t + 3) * RS2 + 2 * lane] = g01;
        }
        __syncwarp();

        // ---- per-lane reduction of one timestep row (64 floats, packed adds) ----
        const ulonglong2* rw = (const ulonglong2*)&redw[lane * RS2];  // 272B offset, 16B aligned
        unsigned long long s0 = 0ull, s1 = 0ull, s2 = 0ull, s3 = 0ull;
#pragma unroll
        for (int j = 0; j < 16; j += 2) {
            ulonglong2 qa = rw[j];
            ulonglong2 qb = rw[j + 1];
            s0 = add2(s0, qa.x);
            s1 = add2(s1, qa.y);
            s2 = add2(s2, qb.x);
            s3 = add2(s3, qb.y);
        }
        s0 = add2(add2(s0, s1), add2(s2, s3));
        float slo, shi;
        unpack2(s0, slo, shi);
        const float s = slo + shi;

        // output for timestep t = lane of this tile (+ skip connection)
        ys[lane * (DPB + 1) + w] = fmaf(Dd, xsw[lane], s);
        __syncthreads();                       // ys ready

        // coalesced store through smem
        yg[(l0 + ld) * D_MODEL] = ys[ld * (DPB + 1) + dl];
    }
}

} // namespace

extern "C" void kernel_launch(void* const* d_in, const int* in_sizes, int n_in,
                              void* d_out, int out_size)
{
    const float* x     = (const float*)d_in[0];
    const float* log_A = (const float*)d_in[1];
    const float* Bp    = (const float*)d_in[2];
    const float* Cp    = (const float*)d_in[3];
    const float* Dp    = (const float*)d_in[4];
    float* y           = (float*)d_out;

    cudaFuncSetAttribute(ssm_scan_kernel,
                         cudaFuncAttributeMaxDynamicSharedMemorySize, SMEM_BYTES);

    dim3 grid(D_MODEL / DPB, BATCH);
    ssm_scan_kernel<<<grid, THREADS, SMEM_BYTES>>>(x, log_A, Bp, Cp, Dp, y);
}

// round 3
// speedup vs baseline: 2.5384x; 2.5384x over previous
#include <cuda_runtime.h>

// VanillaSSM via exact diagonal recurrence (== reference FFT conv):
//   u[d,n](l) = A_bar[d,n]*u(l-1) + x[b,l,d]          (unscaled state)
//   y[b,l,d]  = sum_n (C*B_bar)[d,n] * u[d,n](l) + D[d]*x[b,l,d]
// A = -exp(log_A); A_bar = exp(DT*A); B_bar = (A_bar-1)/A * B_param.
//
// Layout: lane owns 8 states (4 packed f32x2 regs: states n=gl*4+j and +32).
// 8 lanes per d ("group"), 4 d per warp, 2 warps per 64-thread block -> 8 d
// per block, grid (128, 8). Reduction over the 8 group lanes via shuffle
// butterfly batched over 8 timesteps -> zero smem wavefronts in the hot path.
// x / y staged through tiny smem tiles for fully-coalesced global access.

namespace {

constexpr int BATCH   = 8;
constexpr int L       = 2048;
constexpr int D_MODEL = 1024;
constexpr int NSTATE  = 64;
constexpr float DT    = 0.1f;

constexpr int DPB     = 8;        // d per block
constexpr int T       = 32;       // timesteps per round
constexpr int NROUNDS = L / T;    // 64
constexpr int THREADS = 64;       // 2 warps
constexpr int XPAD    = 36;       // xs row stride (floats), d-major rows of 32 t
constexpr int YPAD    = 12;       // ys row stride (floats), t-major rows of 8 d

__device__ __forceinline__ unsigned long long pack2(float lo, float hi) {
    unsigned long long r;
    asm("mov.b64 %0, {%1, %2};" : "=l"(r) : "f"(lo), "f"(hi));
    return r;
}
__device__ __forceinline__ void unpack2(unsigned long long v, float& lo, float& hi) {
    asm("mov.b64 {%0, %1}, %2;" : "=f"(lo), "=f"(hi) : "l"(v));
}
__device__ __forceinline__ unsigned long long mul2(unsigned long long a, unsigned long long b) {
    unsigned long long r;
    asm("mul.rn.f32x2 %0, %1, %2;" : "=l"(r) : "l"(a), "l"(b));
    return r;
}
__device__ __forceinline__ unsigned long long fma2(unsigned long long a, unsigned long long b,
                                                   unsigned long long c) {
    unsigned long long r;
    asm("fma.rn.f32x2 %0, %1, %2, %3;" : "=l"(r) : "l"(a), "l"(b), "l"(c));
    return r;
}

__global__ __launch_bounds__(THREADS)
void ssm_scan_kernel(const float* __restrict__ x,
                     const float* __restrict__ log_A,
                     const float* __restrict__ Bp,
                     const float* __restrict__ Cp,
                     const float* __restrict__ Dp,
                     float* __restrict__ y)
{
    __shared__ float xs[DPB * XPAD];      // xs[d_local][t]
    __shared__ float ys[T * YPAD];        // ys[t][d_local]

    const int b    = blockIdx.y;
    const int d0   = blockIdx.x * DPB;
    const int tid  = threadIdx.x;
    const int w    = tid >> 5;
    const int lane = tid & 31;
    const int g    = lane >> 3;           // group (d) within warp: 0..3
    const int gl   = lane & 7;            // lane within group
    const int dl   = w * 4 + g;           // d_local: 0..7
    const int d    = d0 + dl;

    // ---- coefficients: lane owns states n = gl*4+j paired with n+32 ----
    const int cb = d * NSTATE + gl * 4;
    const float4 laL = *(const float4*)&log_A[cb];
    const float4 laH = *(const float4*)&log_A[cb + 32];
    const float4 bL  = *(const float4*)&Bp[cb];
    const float4 bH  = *(const float4*)&Bp[cb + 32];
    const float4 cL  = *(const float4*)&Cp[cb];
    const float4 cH  = *(const float4*)&Cp[cb + 32];

    unsigned long long a01[4], k01[4];
    {
        const float* laLp = &laL.x; const float* laHp = &laH.x;
        const float* bLp  = &bL.x;  const float* bHp  = &bH.x;
        const float* cLp  = &cL.x;  const float* cHp  = &cH.x;
#pragma unroll
        for (int j = 0; j < 4; ++j) {
            const float AL = -expf(laLp[j]);
            const float AH = -expf(laHp[j]);
            const float aL = expf(DT * AL);
            const float aH = expf(DT * AH);
            const float kL = (aL - 1.0f) / AL * bLp[j] * cLp[j];   // C*B_bar
            const float kH = (aH - 1.0f) / AH * bHp[j] * cHp[j];
            a01[j] = pack2(aL, aH);
            k01[j] = pack2(kL, kH);
        }
    }

    // staging role: thread -> (d = tid%8, l = tid/8 + 8*j)
    const int sd = tid & 7;
    const int sl = tid >> 3;
    const float Dd = Dp[d0 + sd];
    const float* xg = x + (long)b * L * D_MODEL + d0 + sd;
    float*       yg = y + (long)b * L * D_MODEL + d0 + sd;

    unsigned long long u0 = 0ull, u1 = 0ull, u2 = 0ull, u3 = 0ull;

    for (int r = 0; r < NROUNDS; ++r) {
        const int l0 = r * T;

        // load x tile (coalesced 32B sectors: 8 consecutive d per l)
        float xv[4];
#pragma unroll
        for (int j = 0; j < 4; ++j)
            xv[j] = xg[(l0 + sl + 8 * j) * D_MODEL];

        __syncthreads();                   // prev round's xs/ys fully consumed
#pragma unroll
        for (int j = 0; j < 4; ++j)
            xs[sd * XPAD + sl + 8 * j] = xv[j];   // conflict-free scatter
        __syncthreads();                   // xs ready

        // ---- core: 32 steps in batches of 8 (one butterfly per batch) ----
#pragma unroll
        for (int tb = 0; tb < T; tb += 8) {
            float v[8];
#pragma unroll
            for (int h = 0; h < 8; h += 4) {
                const float4 xq = *(const float4*)&xs[dl * XPAD + tb + h];
                const float* xe = &xq.x;
#pragma unroll
                for (int i = 0; i < 4; ++i) {
                    const unsigned long long xx = pack2(xe[i], xe[i]);
                    u0 = fma2(a01[0], u0, xx);
                    u1 = fma2(a01[1], u1, xx);
                    u2 = fma2(a01[2], u2, xx);
                    u3 = fma2(a01[3], u3, xx);
                    unsigned long long acc = mul2(k01[0], u0);
                    acc = fma2(k01[1], u1, acc);
                    acc = fma2(k01[2], u2, acc);
                    acc = fma2(k01[3], u3, acc);
                    float lo, hi;
                    unpack2(acc, lo, hi);
                    v[h + i] = lo + hi;
                }
            }

            // butterfly reduction over the 8 group lanes, batched over 8 t.
            // lane (gl) ends holding y-partial for t = tb + gl.
            {
                const bool h4 = (gl & 4) != 0;
#pragma unroll
                for (int i = 0; i < 4; ++i) {
                    const float send = h4 ? v[i] : v[i + 4];
                    const float keep = h4 ? v[i + 4] : v[i];
                    v[i] = keep + __shfl_xor_sync(0xFFFFFFFFu, send, 4);
                }
                const bool h2 = (gl & 2) != 0;
#pragma unroll
                for (int i = 0; i < 2; ++i) {
                    const float send = h2 ? v[i] : v[i + 2];
                    const float keep = h2 ? v[i + 2] : v[i];
                    v[i] = keep + __shfl_xor_sync(0xFFFFFFFFu, send, 2);
                }
                const bool h1 = (gl & 1) != 0;
                {
                    const float send = h1 ? v[0] : v[1];
                    const float keep = h1 ? v[1] : v[0];
                    v[0] = keep + __shfl_xor_sync(0xFFFFFFFFu, send, 1);
                }
            }
            ys[(tb + gl) * YPAD + dl] = v[0];
        }
        __syncthreads();                   // ys ready

        // coalesced store with fused skip connection y = sum + D*x
#pragma unroll
        for (int j = 0; j < 4; ++j) {
            const float s = ys[(sl + 8 * j) * YPAD + sd];
            yg[(l0 + sl + 8 * j) * D_MODEL] = fmaf(Dd, xv[j], s);
        }
    }
}

} // namespace

extern "C" void kernel_launch(void* const* d_in, const int* in_sizes, int n_in,
                              void* d_out, int out_size)
{
    const float* x     = (const float*)d_in[0];
    const float* log_A = (const float*)d_in[1];
    const float* Bp    = (const float*)d_in[2];
    const float* Cp    = (const float*)d_in[3];
    const float* Dp    = (const float*)d_in[4];
    float* y           = (float*)d_out;

    dim3 grid(D_MODEL / DPB, BATCH);
    ssm_scan_kernel<<<grid, THREADS>>>(x, log_A, Bp, Cp, Dp, y);
}

// round 4
// speedup vs baseline: 2.5593x; 1.0082x over previous
#include <cuda_runtime.h>

// VanillaSSM via exact diagonal recurrence (== reference FFT conv):
//   u[d,n](l) = A_bar[d,n]*u(l-1) + x[b,l,d]
//   y[b,l,d]  = sum_n (C*B_bar)[d,n]*u[d,n](l) + D[d]*x[b,l,d]
// A = -exp(log_A); A_bar = exp(DT*A); B_bar = (A_bar-1)/A * B_param.
//
// Warp-autonomous: each warp owns 4 d-streams for one b. Lane owns 8 states
// (4 packed f32x2 regs); 8 lanes per d. Per 32-step round: x tile prefetched
// a round ahead (LDG never on critical path), staged in warp-private
// double-buffered smem (syncwarp only, no block barriers). Outputs reduced
// across the 8 group lanes with a shuffle butterfly batched over 16 steps,
// then moved to store layout with one shuffle transpose; skip connection
// fused at the store using the kept prefetch registers.

namespace {

constexpr int BATCH   = 8;
constexpr int L       = 2048;
constexpr int D_MODEL = 1024;
constexpr int NSTATE  = 64;
constexpr float DT    = 0.1f;

constexpr int T       = 32;        // timesteps per round
constexpr int NROUNDS = L / T;     // 64
constexpr int THREADS = 64;        // 2 warps/block; 8 d per block
constexpr int XSTR    = 40;        // per-group row stride (floats): 8j+i bank-bijective

__device__ __forceinline__ unsigned long long pack2(float lo, float hi) {
    unsigned long long r;
    asm("mov.b64 %0, {%1, %2};" : "=l"(r) : "f"(lo), "f"(hi));
    return r;
}
__device__ __forceinline__ void unpack2(unsigned long long v, float& lo, float& hi) {
    asm("mov.b64 {%0, %1}, %2;" : "=f"(lo), "=f"(hi) : "l"(v));
}
__device__ __forceinline__ unsigned long long mul2(unsigned long long a, unsigned long long b) {
    unsigned long long r;
    asm("mul.rn.f32x2 %0, %1, %2;" : "=l"(r) : "l"(a), "l"(b));
    return r;
}
__device__ __forceinline__ unsigned long long fma2(unsigned long long a, unsigned long long b,
                                                   unsigned long long c) {
    unsigned long long r;
    asm("fma.rn.f32x2 %0, %1, %2, %3;" : "=l"(r) : "l"(a), "l"(b), "l"(c));
    return r;
}

__global__ __launch_bounds__(THREADS)
void ssm_scan_kernel(const float* __restrict__ x,
                     const float* __restrict__ log_A,
                     const float* __restrict__ Bp,
                     const float* __restrict__ Cp,
                     const float* __restrict__ Dp,
                     float* __restrict__ y)
{
    __shared__ float xs[2][2][4 * XSTR];   // [warp][buf][group*XSTR + t]

    const int b    = blockIdx.y;
    const int tid  = threadIdx.x;
    const int w    = tid >> 5;
    const int lane = tid & 31;
    const int g    = lane >> 3;            // d-group within warp (0..3)
    const int gl   = lane & 7;             // lane within group
    const int d0w  = blockIdx.x * 8 + w * 4;
    const int d    = d0w + g;

    // ---- coefficients: lane owns states n = gl*4+j paired with n+32 ----
    unsigned long long a01[4], k01[4];
    {
        const int cb = d * NSTATE + gl * 4;
        const float4 laL = *(const float4*)&log_A[cb];
        const float4 laH = *(const float4*)&log_A[cb + 32];
        const float4 bL  = *(const float4*)&Bp[cb];
        const float4 bH  = *(const float4*)&Bp[cb + 32];
        const float4 cL  = *(const float4*)&Cp[cb];
        const float4 cH  = *(const float4*)&Cp[cb + 32];
        const float* laLp = &laL.x; const float* laHp = &laH.x;
        const float* bLp  = &bL.x;  const float* bHp  = &bH.x;
        const float* cLp  = &cL.x;  const float* cHp  = &cH.x;
#pragma unroll
        for (int j = 0; j < 4; ++j) {
            const float AL = -expf(laLp[j]);
            const float AH = -expf(laHp[j]);
            const float aL = expf(DT * AL);
            const float aH = expf(DT * AH);
            const float kL = (aL - 1.0f) / AL * bLp[j] * cLp[j];
            const float kH = (aH - 1.0f) / AH * bHp[j] * cHp[j];
            a01[j] = pack2(aL, aH);
            k01[j] = pack2(kL, kH);
        }
    }

    // staging role: lane = si*4 + sj  ->  (l = l0 + si + 8k, d = d0w + sj)
    const int si = lane >> 2;
    const int sj = lane & 3;
    const float Dd = Dp[d0w + sj];
    const float* xg = x + (long)b * L * D_MODEL + d0w + sj;
    float*       yg = y + (long)b * L * D_MODEL + d0w + sj;

    // prefetch tile 0
    float xpre[4], xcur[4];
#pragma unroll
    for (int k = 0; k < 4; ++k)
        xpre[k] = xg[(si + 8 * k) * D_MODEL];

    unsigned long long u0 = 0ull, u1 = 0ull, u2 = 0ull, u3 = 0ull;

    for (int r = 0; r < NROUNDS; ++r) {
        const int l0 = r * T;
        float* xb = xs[w][r & 1];

        // stage tile r (conflict-free: addr mod 32 = 8*sj + si, bijective)
#pragma unroll
        for (int k = 0; k < 4; ++k) {
            xcur[k] = xpre[k];
            xb[sj * XSTR + si + 8 * k] = xpre[k];
        }
        __syncwarp();

        // prefetch tile r+1 (overlaps with the 32-step compute below)
        if (r + 1 < NROUNDS) {
#pragma unroll
            for (int k = 0; k < 4; ++k)
                xpre[k] = xg[(l0 + T + si + 8 * k) * D_MODEL];
        }

        float y_out[4];
#pragma unroll
        for (int tb = 0; tb < T; tb += 16) {
            float v[16];
#pragma unroll
            for (int q = 0; q < 16; q += 4) {
                const float4 xq = *(const float4*)&xb[g * XSTR + tb + q];
                const float* xe = &xq.x;
#pragma unroll
                for (int i2 = 0; i2 < 4; ++i2) {
                    const unsigned long long xx = pack2(xe[i2], xe[i2]);
                    u0 = fma2(a01[0], u0, xx);
                    u1 = fma2(a01[1], u1, xx);
                    u2 = fma2(a01[2], u2, xx);
                    u3 = fma2(a01[3], u3, xx);
                    unsigned long long acc = mul2(k01[0], u0);
                    acc = fma2(k01[1], u1, acc);
                    acc = fma2(k01[2], u2, acc);
                    acc = fma2(k01[3], u3, acc);
                    float lo, hi;
                    unpack2(acc, lo, hi);
                    v[q + i2] = lo + hi;
                }
            }

            // butterfly over the 8 group lanes, 16 timesteps at once.
            // ends: v[0] = y-partial(t=tb+gl), v[8] = y-partial(t=tb+8+gl)
            {
                const bool h4 = (gl & 4) != 0;
#pragma unroll
                for (int ii = 0; ii < 8; ++ii) {
                    const int i = (ii < 4) ? ii : ii + 4;      // {0..3, 8..11}
                    const float send = h4 ? v[i] : v[i + 4];
                    const float keep = h4 ? v[i + 4] : v[i];
                    v[i] = keep + __shfl_xor_sync(0xFFFFFFFFu, send, 4);
                }
                const bool h2 = (gl & 2) != 0;
#pragma unroll
                for (int ii = 0; ii < 4; ++ii) {
                    const int i = (ii < 2) ? ii : ii + 6;      // {0,1, 8,9}
                    const float send = h2 ? v[i] : v[i + 2];
                    const float keep = h2 ? v[i + 2] : v[i];
                    v[i] = keep + __shfl_xor_sync(0xFFFFFFFFu, send, 2);
                }
                const bool h1 = (gl & 1) != 0;
#pragma unroll
                for (int ii = 0; ii < 2; ++ii) {
                    const int i = ii * 8;                      // {0, 8}
                    const float send = h1 ? v[i] : v[i + 1];
                    const float keep = h1 ? v[i + 1] : v[i];
                    v[i] = keep + __shfl_xor_sync(0xFFFFFFFFu, send, 1);
                }
            }

            // transpose to store layout: dst lane (si,sj) takes from lane sj*8+si
            const int srcLane = sj * 8 + si;
            y_out[tb / 8]     = __shfl_sync(0xFFFFFFFFu, v[0], srcLane);
            y_out[tb / 8 + 1] = __shfl_sync(0xFFFFFFFFu, v[8], srcLane);
        }

        // store tile r with fused skip connection
#pragma unroll
        for (int k = 0; k < 4; ++k)
            yg[(l0 + si + 8 * k) * D_MODEL] = fmaf(Dd, xcur[k], y_out[k]);
    }
}

} // namespace

extern "C" void kernel_launch(void* const* d_in, const int* in_sizes, int n_in,
                              void* d_out, int out_size)
{
    const float* x     = (const float*)d_in[0];
    const float* log_A = (const float*)d_in[1];
    const float* Bp    = (const float*)d_in[2];
    const float* Cp    = (const float*)d_in[3];
    const float* Dp    = (const float*)d_in[4];
    float* y           = (float*)d_out;

    dim3 grid(D_MODEL / 8, BATCH);
    ssm_scan_kernel<<<grid, THREADS>>>(x, log_A, Bp, Cp, Dp, y);
}